// round 3
// baseline (speedup 1.0000x reference)
#include <cuda_runtime.h>
#include <math.h>

#define BB 64
#define SS 64
#define EE 256
#define HH 512
#define VV 30000
#define TT 32
#define GG 1536          // 3*H
#define NBLK_FC 235      // ceil(30000/128)

// ---------------- persistent scratch (device globals; no allocs) ----------------
__device__ float g_ex[BB*SS*EE];
__device__ float g_gi[BB*SS*GG];
__device__ float g_enc[BB*SS*HH];
__device__ float g_temp[BB*SS*HH];
__device__ float g_h[BB*HH];
__device__ float g_v[BB*1280];           // [emb(256)|ctx(512)|h(512)]
__device__ float g_u[BB*1024];           // [h(512)|ctx(512)]
__device__ float g_pa[4*BB*GG];
__device__ float g_pb[4*BB*GG];
__device__ float g_pmax[BB*256];
__device__ int   g_pidx[BB*256];

__device__ __forceinline__ float sigmoidf_(float x){ return 1.0f/(1.0f+expf(-x)); }

__global__ __launch_bounds__(64) void k_embed(const int* __restrict__ x,
                                              const float* __restrict__ emb){
    int i = blockIdx.x;
    int tok = x[i];
    const float4* s = (const float4*)(emb + (size_t)tok*EE);
    float4* d = (float4*)(g_ex + (size_t)i*EE);
    d[threadIdx.x] = s[threadIdx.x];
}

__global__ __launch_bounds__(512) void k_zero_h(){
    g_h[blockIdx.x*HH + threadIdx.x] = 0.0f;
}

// C[M,N] = A[M,K] @ W[N,K]^T + bias.  which==0: A=g_ex->g_gi ; which==1: A=g_enc->g_temp
__global__ __launch_bounds__(256) void k_sgemm(int which,
    const float* __restrict__ W, int ldw, const float* __restrict__ bias,
    int N, int K)
{
    const float* A; float* C; int lda, ldc;
    if (which == 0) { A = g_ex;  lda = EE; C = g_gi;   ldc = GG; }
    else            { A = g_enc; lda = HH; C = g_temp; ldc = HH; }

    __shared__ float As[16][64];
    __shared__ float Ws[16][64];
    int tid = threadIdx.x;
    int tx = tid & 15, ty = tid >> 4;
    int n0 = blockIdx.x * 64, m0 = blockIdx.y * 64;
    int lr = tid >> 2, lk = (tid & 3) << 2;
    float acc[4][4] = {};
    const float* Ap = A + (size_t)(m0 + lr)*lda + lk;
    const float* Wp = W + (size_t)(n0 + lr)*ldw + lk;

    for (int k0 = 0; k0 < K; k0 += 16) {
        float4 a4 = *(const float4*)(Ap + k0);
        float4 w4 = *(const float4*)(Wp + k0);
        As[lk+0][lr]=a4.x; As[lk+1][lr]=a4.y; As[lk+2][lr]=a4.z; As[lk+3][lr]=a4.w;
        Ws[lk+0][lr]=w4.x; Ws[lk+1][lr]=w4.y; Ws[lk+2][lr]=w4.z; Ws[lk+3][lr]=w4.w;
        __syncthreads();
        #pragma unroll
        for (int k = 0; k < 16; k++) {
            float4 a = *(const float4*)&As[k][ty<<2];
            float4 b = *(const float4*)&Ws[k][tx<<2];
            float av[4]={a.x,a.y,a.z,a.w}, bv[4]={b.x,b.y,b.z,b.w};
            #pragma unroll
            for (int i=0;i<4;i++)
                #pragma unroll
                for (int j=0;j<4;j++) acc[i][j] += av[i]*bv[j];
        }
        __syncthreads();
    }
    #pragma unroll
    for (int i=0;i<4;i++){
        int m = m0 + (ty<<2) + i;
        #pragma unroll
        for (int j=0;j<4;j++){
            int n = n0 + (tx<<2) + j;
            C[(size_t)m*ldc + n] = acc[i][j] + bias[n];
        }
    }
}

// K-split small-M GEMM: M=64, N=1536, grid (48, 4). Partials -> g_pa/g_pb.
// which==0: A=g_h (lda=512); which==1: A=g_v (lda=1280); which==2: A=g_v+768 (lda=1280)
__global__ __launch_bounds__(256) void k_sgemm_ks(int which,
    const float* __restrict__ W, int ldw, int kchunk)
{
    const float* A; float* Cp; int lda;
    if (which == 0)      { A = g_h;       lda = HH;   Cp = g_pa; }
    else if (which == 1) { A = g_v;       lda = 1280; Cp = g_pa; }
    else                 { A = g_v + 768; lda = 1280; Cp = g_pb; }

    __shared__ float As[16][64];
    __shared__ float Ws[16][32];
    int tid = threadIdx.x;
    int n0 = blockIdx.x * 32, kb = blockIdx.y;
    int tx = tid & 15, ty = tid >> 4;
    int ar = tid >> 2, ak = (tid & 3) << 2;
    float acc[4][2] = {};
    const float* Ap = A + (size_t)ar*lda + ak;
    int k_lo = kb * kchunk, k_hi = k_lo + kchunk;

    for (int k0 = k_lo; k0 < k_hi; k0 += 16) {
        float4 a4 = *(const float4*)(Ap + k0);
        As[ak+0][ar]=a4.x; As[ak+1][ar]=a4.y; As[ak+2][ar]=a4.z; As[ak+3][ar]=a4.w;
        if (tid < 128) {
            int wr = tid >> 2, wk = (tid & 3) << 2;
            float4 w4 = *(const float4*)(W + (size_t)(n0 + wr)*ldw + k0 + wk);
            Ws[wk+0][wr]=w4.x; Ws[wk+1][wr]=w4.y; Ws[wk+2][wr]=w4.z; Ws[wk+3][wr]=w4.w;
        }
        __syncthreads();
        #pragma unroll
        for (int k=0;k<16;k++){
            float4 a = *(const float4*)&As[k][ty<<2];
            float2 b = *(const float2*)&Ws[k][tx<<1];
            acc[0][0]+=a.x*b.x; acc[0][1]+=a.x*b.y;
            acc[1][0]+=a.y*b.x; acc[1][1]+=a.y*b.y;
            acc[2][0]+=a.z*b.x; acc[2][1]+=a.z*b.y;
            acc[3][0]+=a.w*b.x; acc[3][1]+=a.w*b.y;
        }
        __syncthreads();
    }
    float* Co = Cp + (size_t)kb*BB*GG;
    #pragma unroll
    for (int i=0;i<4;i++){
        int m = (ty<<2)+i, n = n0 + (tx<<1);
        Co[(size_t)m*GG + n]   = acc[i][0];
        Co[(size_t)m*GG + n+1] = acc[i][1];
    }
}

__global__ __launch_bounds__(256) void k_enc_gates(int t, const float* __restrict__ bhh){
    int idx = blockIdx.x*256 + threadIdx.x;
    int b = idx >> 9, j = idx & 511;
    float hr=0.f, hz=0.f, hn=0.f;
    #pragma unroll
    for (int kb=0;kb<4;kb++){
        const float* p = g_pa + ((size_t)kb*BB + b)*GG;
        hr += p[j]; hz += p[HH+j]; hn += p[2*HH+j];
    }
    const float* gi = g_gi + ((size_t)(b*SS + t))*GG;
    float r = sigmoidf_(gi[j]    + hr + bhh[j]);
    float z = sigmoidf_(gi[HH+j] + hz + bhh[HH+j]);
    float n = tanhf(gi[2*HH+j] + r*(hn + bhh[2*HH+j]));
    float h = g_h[b*HH + j];
    float hnew = (1.0f - z)*n + z*h;
    g_h[b*HH + j] = hnew;
    g_enc[((size_t)(b*SS + t))*HH + j] = hnew;
}

__global__ __launch_bounds__(256) void k_dec_gates(const float* __restrict__ bih,
                                                   const float* __restrict__ bhh){
    int idx = blockIdx.x*256 + threadIdx.x;
    int b = idx >> 9, j = idx & 511;
    float ir=0.f, iz=0.f, in_=0.f, hr=0.f, hz=0.f, hn=0.f;
    #pragma unroll
    for (int kb=0;kb<4;kb++){
        const float* pa = g_pa + ((size_t)kb*BB + b)*GG;
        const float* pb = g_pb + ((size_t)kb*BB + b)*GG;
        ir += pa[j]; iz += pa[HH+j]; in_ += pa[2*HH+j];
        hr += pb[j]; hz += pb[HH+j]; hn  += pb[2*HH+j];
    }
    float r = sigmoidf_(ir + bih[j]    + hr + bhh[j]);
    float z = sigmoidf_(iz + bih[HH+j] + hz + bhh[HH+j]);
    float n = tanhf(in_ + bih[2*HH+j] + r*(hn + bhh[2*HH+j]));
    float h = g_v[b*1280 + 768 + j];
    float hnew = (1.0f - z)*n + z*h;
    g_v[b*1280 + 768 + j] = hnew;
    g_u[b*1024 + j]       = hnew;
    g_h[b*HH + j]         = hnew;
}

__global__ __launch_bounds__(512) void k_init_dec(const int* __restrict__ sd,
                                                  const float* __restrict__ emb){
    int b = blockIdx.x, j = threadIdx.x;
    float h = g_h[b*HH + j];
    g_v[b*1280 + 256 + j] = h;
    g_v[b*1280 + 768 + j] = h;
    g_u[b*1024 + 512 + j] = h;
    if (j < EE) {
        int tok = sd[b];
        g_v[b*1280 + j] = emb[(size_t)tok*EE + j];
    }
}

// fc: score[64,30000] = g_u[64,1024] @ fc_W^T + b ; write out rows; per-block partial argmax
__global__ __launch_bounds__(256) void k_fc(const float* __restrict__ Wf,
    const float* __restrict__ bias, float* __restrict__ out, int t)
{
    __shared__ float As[16][64];
    __shared__ float Ws[16][128];
    int tid = threadIdx.x;
    int n0 = blockIdx.x << 7;
    int tx = tid & 15, ty = tid >> 4;
    int ar = tid >> 2, ak = (tid & 3) << 2;
    int wrl = tid >> 2, wkl = (tid & 3) << 2;
    float acc[4][8] = {};
    const float* Ap = g_u + (size_t)ar*1024 + ak;

    for (int k0 = 0; k0 < 1024; k0 += 16) {
        float4 a4 = *(const float4*)(Ap + k0);
        As[ak+0][ar]=a4.x; As[ak+1][ar]=a4.y; As[ak+2][ar]=a4.z; As[ak+3][ar]=a4.w;
        #pragma unroll
        for (int p=0;p<2;p++){
            int wr = (p<<6) + wrl;
            int wn = n0 + wr;
            float4 w4 = (wn < VV) ? *(const float4*)(Wf + (size_t)wn*1024 + k0 + wkl)
                                  : make_float4(0.f,0.f,0.f,0.f);
            Ws[wkl+0][wr]=w4.x; Ws[wkl+1][wr]=w4.y; Ws[wkl+2][wr]=w4.z; Ws[wkl+3][wr]=w4.w;
        }
        __syncthreads();
        #pragma unroll
        for (int k=0;k<16;k++){
            float4 a  = *(const float4*)&As[k][ty<<2];
            float4 b0 = *(const float4*)&Ws[k][tx<<2];
            float4 b1 = *(const float4*)&Ws[k][64 + (tx<<2)];
            float av[4]={a.x,a.y,a.z,a.w};
            float bv[8]={b0.x,b0.y,b0.z,b0.w,b1.x,b1.y,b1.z,b1.w};
            #pragma unroll
            for (int i=0;i<4;i++)
                #pragma unroll
                for (int j=0;j<8;j++) acc[i][j] += av[i]*bv[j];
        }
        __syncthreads();
    }

    float bestv[4]; int besti[4];
    #pragma unroll
    for (int i=0;i<4;i++){
        int b = (ty<<2) + i;
        size_t orow = ((size_t)(b*TT + t))*VV;
        float bv = -3.0e38f; int bi = 0x7fffffff;
        #pragma unroll
        for (int j=0;j<8;j++){
            int n = n0 + ((j<4) ? ((tx<<2)+j) : (64+(tx<<2)+(j-4)));
            if (n < VV){
                float val = acc[i][j] + bias[n];
                out[orow + n] = val;
                if (val > bv || (val == bv && n < bi)) { bv = val; bi = n; }
            }
        }
        bestv[i]=bv; besti[i]=bi;
    }
    __syncthreads();
    float* sv = (float*)Ws;
    int*   si = (int*)As;
    #pragma unroll
    for (int i=0;i<4;i++){
        int b=(ty<<2)+i;
        sv[b*16+tx]=bestv[i];
        si[b*16+tx]=besti[i];
    }
    __syncthreads();
    if (tid < 64){
        float bv=-3.0e38f; int bi=0x7fffffff;
        #pragma unroll 4
        for (int c=0;c<16;c++){
            float v=sv[tid*16+c]; int ii=si[tid*16+c];
            if (v>bv || (v==bv && ii<bi)){bv=v;bi=ii;}
        }
        g_pmax[tid*256 + blockIdx.x] = bv;
        g_pidx[tid*256 + blockIdx.x] = bi;
    }
}

__global__ __launch_bounds__(256) void k_argmax(const float* __restrict__ emb){
    int b = blockIdx.x, tid = threadIdx.x;
    __shared__ float sv[256];
    __shared__ int   si[256];
    float v = -3.4e38f; int idx = 0x7fffffff;
    if (tid < NBLK_FC){ v = g_pmax[b*256+tid]; idx = g_pidx[b*256+tid]; }
    sv[tid]=v; si[tid]=idx;
    __syncthreads();
    for (int o=128;o>0;o>>=1){
        if (tid < o){
            float v2=sv[tid+o]; int i2=si[tid+o];
            if (v2>sv[tid] || (v2==sv[tid] && i2<si[tid])){ sv[tid]=v2; si[tid]=i2; }
        }
        __syncthreads();
    }
    int tok = si[0];
    g_v[b*1280 + tid] = emb[(size_t)tok*EE + tid];
}

__global__ __launch_bounds__(512) void k_attn(){
    int b = blockIdx.x, tid = threadIdx.x;
    int w = tid >> 5, lane = tid & 31;
    __shared__ float sc[SS];
    const float* hb = g_h + b*HH;
    #pragma unroll
    for (int r = 0; r < 4; r++){
        int s = w*4 + r;
        const float* tp = g_temp + ((size_t)(b*SS+s))*HH;
        float acc = 0.f;
        for (int j = lane; j < HH; j += 32) acc += tp[j]*hb[j];
        #pragma unroll
        for (int o=16;o>0;o>>=1) acc += __shfl_xor_sync(0xffffffffu, acc, o);
        if (lane==0) sc[s] = acc;
    }
    __syncthreads();
    if (w == 0){
        float v0 = sc[lane], v1 = sc[lane+32];
        float m = fmaxf(v0,v1);
        #pragma unroll
        for(int o=16;o>0;o>>=1) m = fmaxf(m, __shfl_xor_sync(0xffffffffu,m,o));
        float e0 = expf(v0-m), e1 = expf(v1-m);
        float s = e0+e1;
        #pragma unroll
        for(int o=16;o>0;o>>=1) s += __shfl_xor_sync(0xffffffffu,s,o);
        sc[lane] = e0/s; sc[lane+32] = e1/s;
    }
    __syncthreads();
    int j = tid;
    const float* eb = g_enc + (size_t)b*SS*HH + j;
    float ctx = 0.f;
    #pragma unroll 8
    for (int s=0;s<SS;s++) ctx += sc[s]*eb[(size_t)s*HH];
    g_v[b*1280 + 256 + j] = ctx;
    g_u[b*1024 + 512 + j] = ctx;
}

extern "C" void kernel_launch(void* const* d_in, const int* in_sizes, int n_in,
                              void* d_out, int out_size){
    // metadata order: x, start_decode, [max_len], emb, enc_Wih, enc_Whh, enc_bih,
    // enc_bhh, dec_Wih, dec_Whh, dec_bih, dec_bhh, fc_W, fc_b, attn_W, attn_b
    int off = (n_in >= 16) ? 1 : 0;   // max_len scalar present at index 2
    const int*   x    = (const int*)d_in[0];
    const int*   sd   = (const int*)d_in[1];
    const float* emb  = (const float*)d_in[2+off];
    const float* eWih = (const float*)d_in[3+off];
    const float* eWhh = (const float*)d_in[4+off];
    const float* ebih = (const float*)d_in[5+off];
    const float* ebhh = (const float*)d_in[6+off];
    const float* dWih = (const float*)d_in[7+off];
    const float* dWhh = (const float*)d_in[8+off];
    const float* dbih = (const float*)d_in[9+off];
    const float* dbhh = (const float*)d_in[10+off];
    const float* fcW  = (const float*)d_in[11+off];
    const float* fcb  = (const float*)d_in[12+off];
    const float* aW   = (const float*)d_in[13+off];
    const float* ab   = (const float*)d_in[14+off];
    float* out = (float*)d_out;

    k_embed<<<BB*SS,64>>>(x, emb);
    k_zero_h<<<BB,512>>>();
    k_sgemm<<<dim3(GG/64, BB*SS/64),256>>>(0, eWih, EE, ebih, GG, EE);
    for (int t=0;t<SS;t++){
        k_sgemm_ks<<<dim3(48,4),256>>>(0, eWhh, HH, 128);
        k_enc_gates<<<128,256>>>(t, ebhh);
    }
    k_sgemm<<<dim3(HH/64, BB*SS/64),256>>>(1, aW, HH, ab, HH, HH);
    k_init_dec<<<BB,512>>>(sd, emb);
    for (int t=0;t<TT;t++){
        k_sgemm_ks<<<dim3(48,4),256>>>(1, dWih, 768, 192);
        k_sgemm_ks<<<dim3(48,4),256>>>(2, dWhh, HH, 128);
        k_dec_gates<<<128,256>>>(dbih, dbhh);
        k_fc<<<NBLK_FC,256>>>(fcW, fcb, out, t);
        k_argmax<<<BB,256>>>(emb);
        k_attn<<<BB,512>>>();
    }
}